// round 11
// baseline (speedup 1.0000x reference)
#include <cuda_runtime.h>
#include <cuda_fp16.h>
#include <cstdint>

// WaveletBlock fused: DWT -> GEMM1(+bias,SiLU) -> GEMM2(+bias) -> IDWT
// fp16 single-pass mma.sync. 1024 CTAs x 512 threads (16 warps), M_tile=64.
// Whole 256x256 W resident in smem; explicit fragment double-buffering.

#define C_   64
#define H_   128
#define W_   128
#define HW_  (H_*W_)

#define ARS  528          // row stride (bytes): 256 fp16 + 16B pad
#define SM_A 0            // A: 64 rows x ARS  = 33792
#define SM_W 33792        // W: 256 rows x ARS = 135168
#define SM_TOTAL 168960

#define NTHR 512

__device__ __half g_Wh[2][256 * 256];

__global__ void prep_half(const float* __restrict__ w0, const float* __restrict__ w1)
{
    int i = blockIdx.x * blockDim.x + threadIdx.x;
    g_Wh[0][i] = __float2half_rn(w0[i]);
    g_Wh[1][i] = __float2half_rn(w1[i]);
}

__device__ __forceinline__ uint32_t smem_u32(const void* p) {
    uint32_t a;
    asm("{ .reg .u64 t; cvta.to.shared.u64 t, %1; cvt.u32.u64 %0, t; }" : "=r"(a) : "l"(p));
    return a;
}
#define LDX4(r, a) \
    asm volatile("ldmatrix.sync.aligned.m8n8.x4.shared.b16 {%0,%1,%2,%3}, [%4];" \
        : "=r"((r)[0]), "=r"((r)[1]), "=r"((r)[2]), "=r"((r)[3]) : "r"(a))
#define LDX2(r, a) \
    asm volatile("ldmatrix.sync.aligned.m8n8.x2.shared.b16 {%0,%1}, [%2];" \
        : "=r"((r)[0]), "=r"((r)[1]) : "r"(a))
#define MMA(c, a, b0, b1) \
    asm volatile("mma.sync.aligned.m16n8k16.row.col.f32.f16.f16.f32 " \
        "{%0,%1,%2,%3},{%4,%5,%6,%7},{%8,%9},{%0,%1,%2,%3};" \
        : "+f"((c)[0]), "+f"((c)[1]), "+f"((c)[2]), "+f"((c)[3]) \
        : "r"((a)[0]), "r"((a)[1]), "r"((a)[2]), "r"((a)[3]), "r"(b0), "r"(b1))
#define CP_COMMIT() asm volatile("cp.async.commit_group;" ::: "memory")
#define CP_WAIT0()  asm volatile("cp.async.wait_group 0;" ::: "memory")
#define CP_WAIT1()  asm volatile("cp.async.wait_group 1;" ::: "memory")

__device__ __forceinline__ uint32_t pack_h2(float a, float b) {
    __half2 h = __floats2half2_rn(a, b);
    return *reinterpret_cast<uint32_t*>(&h);
}
__device__ __forceinline__ float silu(float v) {
    return v * (1.0f / (1.0f + __expf(-v)));
}

// copy one k-half (half*128 fp16 cols) of 256x256 W into smem
__device__ __forceinline__ void copy_W_half(uint32_t dstbase,
                                            const __half* __restrict__ Wg,
                                            int half, int tid)
{
    #pragma unroll
    for (int i = 0; i < 8; ++i) {
        int id = i * NTHR + tid;               // 0..4095
        int n = id >> 4, c = (id & 15) + half * 16;
        const __half* src = Wg + n * 256 + c * 8;
        uint32_t dst = dstbase + (uint32_t)n * ARS + c * 16;
        asm volatile("cp.async.cg.shared.global [%0], [%1], 16;" :: "r"(dst), "l"(src) : "memory");
    }
}

// GEMM over k-steps [KS0,KS1): acc[i][q] covers m=mw*32+i*16.., n=q*64+nw*8..
// Explicit register double-buffering of A/B fragments.
template<int KS0, int KS1>
__device__ __forceinline__ void gemm_range(uint32_t sb, float acc[2][4][4],
                                           int l, int mw, int nw)
{
    const uint32_t aBase = sb + SM_A
        + (uint32_t)(mw * 32 + ((l >> 3) & 1) * 8 + (l & 7)) * ARS
        + ((l >> 4) & 1) * 16;
    const int ll = l & 15;
    const uint32_t bBase = sb + SM_W
        + (uint32_t)(nw * 8 + (ll & 7)) * ARS + ((ll >> 3) & 1) * 16;

    uint32_t Af[2][2][4], Bf[2][4][2];
    #pragma unroll
    for (int i = 0; i < 2; ++i)
        LDX4(Af[0][i], aBase + (uint32_t)i * (16 * ARS) + KS0 * 32);
    #pragma unroll
    for (int q = 0; q < 4; ++q)
        LDX2(Bf[0][q], bBase + (uint32_t)q * (64 * ARS) + KS0 * 32);

    #pragma unroll
    for (int ks = KS0; ks < KS1; ++ks) {
        const int cur = (ks - KS0) & 1, nxt = cur ^ 1;
        if (ks + 1 < KS1) {
            #pragma unroll
            for (int i = 0; i < 2; ++i)
                LDX4(Af[nxt][i], aBase + (uint32_t)i * (16 * ARS) + (ks + 1) * 32);
            #pragma unroll
            for (int q = 0; q < 4; ++q)
                LDX2(Bf[nxt][q], bBase + (uint32_t)q * (64 * ARS) + (ks + 1) * 32);
        }
        #pragma unroll
        for (int i = 0; i < 2; ++i)
            #pragma unroll
            for (int q = 0; q < 4; ++q)
                MMA(acc[i][q], Af[cur][i], Bf[cur][q][0], Bf[cur][q][1]);
    }
}

extern "C" __global__ void __launch_bounds__(NTHR, 1)
wavelet_mma(const float* __restrict__ x,
            const float* __restrict__ conv_b,
            const float* __restrict__ conv_out_b,
            float* __restrict__ out)
{
    extern __shared__ char sm[];
    const uint32_t sb = smem_u32(sm);
    const int tid = threadIdx.x;
    const int l  = tid & 31, wid = tid >> 5;
    const int nw = wid & 7,  mw  = wid >> 3;   // 8 n-warps x 2 m-warps
    const int blk = blockIdx.x;
    const int n_img = blk >> 6, hh = blk & 63;
    const size_t img_off = (size_t)n_img * C_ * HW_;
    const float* xb = x + img_off + (size_t)(2 * hh) * W_;

    // fetch W1 (two k-halves) while we do the DWT
    copy_W_half(sb + SM_W, g_Wh[0], 0, tid); CP_COMMIT();
    copy_W_half(sb + SM_W, g_Wh[0], 1, tid); CP_COMMIT();

    // ---- DWT -> A fp16 [m=64][k=256] ----
    #pragma unroll
    for (int i = 0; i < 4; ++i) {
        int e = i * NTHR + tid;            // 0..2047
        int cpair = e >> 6, wh = e & 63;
        int c0 = cpair * 2;
        const float* px = xb + (size_t)c0 * HW_ + 2 * wh;
        float2 t0 = *(const float2*)px,         b0 = *(const float2*)(px + W_);
        float2 t1 = *(const float2*)(px + HW_), b1 = *(const float2*)(px + HW_ + W_);
        float x1 = t0.x * 0.5f, x3 = t0.y * 0.5f, x2 = b0.x * 0.5f, x4 = b0.y * 0.5f;
        float qa[4] = { x1 + x2 + x3 + x4, -x1 - x2 + x3 + x4,
                       -x1 + x2 - x3 + x4,  x1 - x2 - x3 + x4};
        x1 = t1.x * 0.5f; x3 = t1.y * 0.5f; x2 = b1.x * 0.5f; x4 = b1.y * 0.5f;
        float qb[4] = { x1 + x2 + x3 + x4, -x1 - x2 + x3 + x4,
                       -x1 + x2 - x3 + x4,  x1 - x2 - x3 + x4};
        #pragma unroll
        for (int q = 0; q < 4; ++q) {
            uint32_t off = (uint32_t)wh * ARS + (uint32_t)(q * 64 + c0) * 2;
            *(uint32_t*)(sm + SM_A + off) = pack_h2(qa[q], qb[q]);
        }
    }

    float acc[2][4][4];
    #pragma unroll
    for (int i = 0; i < 2; ++i)
        #pragma unroll
        for (int q = 0; q < 4; ++q)
            #pragma unroll
            for (int r = 0; r < 4; ++r) acc[i][q][r] = 0.f;

    CP_WAIT0();
    __syncthreads();

    // ---- GEMM1 ----
    gemm_range<0, 16>(sb, acc, l, mw, nw);

    __syncthreads();                 // all W1 / A reads done

    // fetch W2 (two k-halves, separate groups), overlapped with epilogue 1
    copy_W_half(sb + SM_W, g_Wh[1], 0, tid); CP_COMMIT();
    copy_W_half(sb + SM_W, g_Wh[1], 1, tid); CP_COMMIT();

    // ---- epilogue 1: bias + SiLU -> A fp16 (feat) ----
    {
        float bv[4][2];
        #pragma unroll
        for (int q = 0; q < 4; ++q)
            #pragma unroll
            for (int cp = 0; cp < 2; ++cp)
                bv[q][cp] = __ldg(conv_b + q * 64 + nw * 8 + (l & 3) * 2 + cp);
        #pragma unroll
        for (int i = 0; i < 2; ++i)
            #pragma unroll
            for (int rh = 0; rh < 2; ++rh) {
                int m = mw * 32 + i * 16 + rh * 8 + (l >> 2);
                #pragma unroll
                for (int q = 0; q < 4; ++q) {
                    float v0 = silu(acc[i][q][rh * 2 + 0] + bv[q][0]);
                    float v1 = silu(acc[i][q][rh * 2 + 1] + bv[q][1]);
                    int col = q * 64 + nw * 8 + (l & 3) * 2;
                    uint32_t off = (uint32_t)m * ARS + (uint32_t)col * 2;
                    *(uint32_t*)(sm + SM_A + off) = pack_h2(v0, v1);
                }
            }
    }
    #pragma unroll
    for (int i = 0; i < 2; ++i)
        #pragma unroll
        for (int q = 0; q < 4; ++q)
            #pragma unroll
            for (int r = 0; r < 4; ++r) acc[i][q][r] = 0.f;

    // ---- GEMM2: first k-half once W2 half-1 landed ----
    CP_WAIT1();
    __syncthreads();
    gemm_range<0, 8>(sb, acc, l, mw, nw);

    CP_WAIT0();
    __syncthreads();
    gemm_range<8, 16>(sb, acc, l, mw, nw);

    // ---- epilogue 2: bias + IDWT + store (regs only) ----
    {
        float bv[4][2];
        #pragma unroll
        for (int q = 0; q < 4; ++q)
            #pragma unroll
            for (int cp = 0; cp < 2; ++cp)
                bv[q][cp] = __ldg(conv_out_b + q * 64 + nw * 8 + (l & 3) * 2 + cp);
        const int r0 = 2 * hh;
        #pragma unroll
        for (int i = 0; i < 2; ++i)
            #pragma unroll
            for (int rh = 0; rh < 2; ++rh) {
                int wh = mw * 32 + i * 16 + rh * 8 + (l >> 2);
                #pragma unroll
                for (int cp = 0; cp < 2; ++cp) {
                    int co = nw * 8 + (l & 3) * 2 + cp;
                    float y1 = (acc[i][0][rh * 2 + cp] + bv[0][cp]) * 0.5f;
                    float y2 = (acc[i][1][rh * 2 + cp] + bv[1][cp]) * 0.5f;
                    float y3 = (acc[i][2][rh * 2 + cp] + bv[2][cp]) * 0.5f;
                    float y4 = (acc[i][3][rh * 2 + cp] + bv[3][cp]) * 0.5f;
                    float va = y1 - y2 - y3 + y4;
                    float vb = y1 - y2 + y3 - y4;
                    float vc = y1 + y2 - y3 - y4;
                    float vd = y1 + y2 + y3 + y4;
                    float* po = out + img_off + (size_t)co * HW_
                              + (size_t)r0 * W_ + 2 * wh;
                    *(float2*)po        = make_float2(va, vc);
                    *(float2*)(po + W_) = make_float2(vb, vd);
                }
            }
    }
}

extern "C" void kernel_launch(void* const* d_in, const int* in_sizes, int n_in,
                              void* d_out, int out_size)
{
    const float* x          = (const float*)d_in[0];
    const float* conv_w     = (const float*)d_in[1];
    const float* conv_b     = (const float*)d_in[2];
    const float* conv_out_w = (const float*)d_in[3];
    const float* conv_out_b = (const float*)d_in[4];
    float* out = (float*)d_out;

    prep_half<<<256, 256>>>(conv_w, conv_out_w);

    cudaFuncSetAttribute(wavelet_mma,
                         cudaFuncAttributeMaxDynamicSharedMemorySize, SM_TOTAL);
    wavelet_mma<<<1024, NTHR, SM_TOTAL>>>(x, conv_b, conv_out_b, out);
}